// round 3
// baseline (speedup 1.0000x reference)
#include <cuda_runtime.h>

// Invert4_10: 16-step spiking scan, elementwise.
//   spike((v-T)/(|v|+1)) == (v > T)      (denominator strictly positive)
//   z in {0,1} -> predicate the updates; pack (v,out) into one 64-bit pair so
//   each step is:  FSETP(v > T_t) ; @p add.rn.f32x2 (v,out) += (-h_{t+1}, d_t)
//   i.e. 2 SASS instructions per step instead of 3.
//   Step 0 peeled: z0 = (|x| > T0 = -0.2537) = 1 always.

// Packed per-step constants: lane0 (v lane) = -h_{t+1}, lane1 (out lane) = d_t.
struct Cs { unsigned long long c[14]; };

static __device__ __forceinline__ unsigned long long pk(float lo, float hi) {
    return (unsigned long long)__float_as_uint(lo) |
           ((unsigned long long)__float_as_uint(hi) << 32);
}

static __device__ __forceinline__ Cs make_cs() {
    Cs C;
    C.c[0]  = pk(-0.9177631f,  0.09543603f);   // t=1 : -h2 , d1
    C.c[1]  = pk(-0.9392744f, -0.00957536f);   // t=2
    C.c[2]  = pk(-0.5681609f, -0.02775419f);   // t=3
    C.c[3]  = pk(-0.9465831f,  0.07635077f);   // t=4
    C.c[4]  = pk(-0.6847087f, -0.02604962f);   // t=5
    C.c[5]  = pk(-0.45589155f, -0.01608226f);  // t=6
    C.c[6]  = pk(-0.57916474f, -0.0154707f);   // t=7
    C.c[7]  = pk(-0.7803396f, -0.01741009f);   // t=8
    C.c[8]  = pk(-0.28270212f, -0.00761568f);  // t=9
    C.c[9]  = pk(-0.49239117f, -0.00868225f);  // t=10
    C.c[10] = pk(-1.1224731f, -0.01600825f);   // t=11
    C.c[11] = pk(-0.5738949f, -0.00795393f);   // t=12
    C.c[12] = pk(-0.32048506f, -0.0046836f);   // t=13
    C.c[13] = pk(-0.2620882f, -0.00339996f);   // t=14
    // Launder: make values opaque so nvcc keeps ONE register copy instead of
    // re-materializing immediates at every inlined use site.
#pragma unroll
    for (int i = 0; i < 14; ++i) asm("" : "+l"(C.c[i]));
    return C;
}

// One packed step: compare v (low lane of s), conditionally add packed const.
#define PSTEP(T, idx)                                  \
    "mov.b64 {v, o}, s;\n\t"                           \
    "setp.gt.f32 p, v, " #T ";\n\t"                    \
    "@p add.rn.f32x2 s, s, %" #idx ";\n\t"

static __device__ __forceinline__ float run1(float x, const Cs& C) {
    float v0 = fabsf(x) - 0.8721661f;   // peeled step 0 (z0=1): v = |x| - h1
    float out;
    asm("{\n\t"
        ".reg .pred p;\n\t"
        ".reg .f32 v, o;\n\t"
        ".reg .b64 s;\n\t"
        "mov.b64 s, {%1, %2};\n\t"      // s = (v, out=d0)
        PSTEP(-0.35691947, 3)
        PSTEP( 0.35702407, 4)
        PSTEP( 1.8097845,  5)
        PSTEP(-0.8933508,  6)
        PSTEP( 0.74517566, 7)
        PSTEP( 0.57702994, 8)
        PSTEP( 0.56928945, 9)
        PSTEP( 0.61470956, 10)
        PSTEP( 0.43903926, 11)
        PSTEP( 0.20668195, 12)
        PSTEP( 0.6593264,  13)
        PSTEP( 0.35631987, 14)
        PSTEP( 0.15981139, 15)
        PSTEP(-0.12464668, 16)
        // last step (t=15): only out is updated (no h16)
        "mov.b64 {v, o}, s;\n\t"
        "setp.gt.f32 p, v, -0.22194518;\n\t"
        "@p add.f32 o, o, -0.00177163;\n\t"
        "mov.f32 %0, o;\n\t"
        "}"
        : "=f"(out)
        : "f"(v0), "f"(0.0931013f),
          "l"(C.c[0]), "l"(C.c[1]), "l"(C.c[2]), "l"(C.c[3]), "l"(C.c[4]),
          "l"(C.c[5]), "l"(C.c[6]), "l"(C.c[7]), "l"(C.c[8]), "l"(C.c[9]),
          "l"(C.c[10]), "l"(C.c[11]), "l"(C.c[12]), "l"(C.c[13]));

    float r = copysignf(out, x);        // single LOP3
    return (x == 0.0f) ? 0.0f : r;      // jnp.sign(0) == 0
}

static __device__ __forceinline__ float4 run4(float4 p, const Cs& C) {
    float4 r;
    r.x = run1(p.x, C);
    r.y = run1(p.y, C);
    r.z = run1(p.z, C);
    r.w = run1(p.w, C);
    return r;
}

// Exact-cover variant: grid covers nvec exactly, no bounds checks.
__global__ void __launch_bounds__(256)
invert_kernel_exact(const float4* __restrict__ x, float4* __restrict__ y) {
    const Cs C = make_cs();
    const int stride = blockDim.x * gridDim.x;
    const int i = blockIdx.x * blockDim.x + threadIdx.x;

    // Front-batched streaming loads (MLP=4); data touched once -> .cs
    float4 a0 = __ldcs(x + i);
    float4 a1 = __ldcs(x + i + stride);
    float4 a2 = __ldcs(x + i + 2 * stride);
    float4 a3 = __ldcs(x + i + 3 * stride);

    __stcs(y + i,              run4(a0, C));
    __stcs(y + i + stride,     run4(a1, C));
    __stcs(y + i + 2 * stride, run4(a2, C));
    __stcs(y + i + 3 * stride, run4(a3, C));
}

// Guarded fallback for non-divisible sizes.
__global__ void __launch_bounds__(256)
invert_kernel_guard(const float4* __restrict__ x, float4* __restrict__ y, int nvec) {
    const Cs C = make_cs();
    const int stride = blockDim.x * gridDim.x;
    const int i = blockIdx.x * blockDim.x + threadIdx.x;
    const int i0 = i, i1 = i + stride, i2 = i + 2 * stride, i3 = i + 3 * stride;

    float4 a0, a1, a2, a3;
    const bool m0 = (i0 < nvec), m1 = (i1 < nvec), m2 = (i2 < nvec), m3 = (i3 < nvec);
    if (m0) a0 = __ldcs(x + i0);
    if (m1) a1 = __ldcs(x + i1);
    if (m2) a2 = __ldcs(x + i2);
    if (m3) a3 = __ldcs(x + i3);

    if (m0) __stcs(y + i0, run4(a0, C));
    if (m1) __stcs(y + i1, run4(a1, C));
    if (m2) __stcs(y + i2, run4(a2, C));
    if (m3) __stcs(y + i3, run4(a3, C));
}

__global__ void invert_tail_kernel(const float* __restrict__ x, float* __restrict__ y,
                                   int start, int n) {
    const Cs C = make_cs();
    int i = start + blockIdx.x * blockDim.x + threadIdx.x;
    if (i < n) y[i] = run1(x[i], C);
}

extern "C" void kernel_launch(void* const* d_in, const int* in_sizes, int n_in,
                              void* d_out, int out_size) {
    const float* x = (const float*)d_in[0];
    float* y = (float*)d_out;
    const long long n = (long long)in_sizes[0];

    const long long nvec = n >> 2;        // float4 count
    const int threads = 256;
    const int vpt = 4;                    // float4 per thread
    const long long per_blk = (long long)threads * vpt;

    if (nvec > 0 && (nvec % per_blk) == 0) {
        invert_kernel_exact<<<(unsigned)(nvec / per_blk), threads>>>(
            (const float4*)x, (float4*)y);
    } else if (nvec > 0) {
        long long blocks = (nvec + per_blk - 1) / per_blk;
        invert_kernel_guard<<<(unsigned)blocks, threads>>>(
            (const float4*)x, (float4*)y, (int)nvec);
    }

    const int rem = (int)(n & 3LL);
    if (rem) {
        invert_tail_kernel<<<1, 32>>>(x, y, (int)(n - rem), (int)n);
    }
}